// round 6
// baseline (speedup 1.0000x reference)
#include <cuda_runtime.h>
#include <math.h>

#define TPB 256

// Prologue-computed operands (k-major [k][out])
__device__ float g_P[128*128];   // (Wq^T Wk)/sqrt(d)
__device__ float g_G[128*128];   // Wv^T Theta^T
__device__ float g_U[128*64];    // [k][j]: j<32 -> (W1q@Wq)[j,k], j>=32 -> (W1k@Wk)[j-32,k]

typedef unsigned long long u64;

__device__ __forceinline__ float4 ld4(const float* p){ return *reinterpret_cast<const float4*>(p); }
__device__ __forceinline__ void st4(float* p, float4 v){ *reinterpret_cast<float4*>(p)=v; }
__device__ __forceinline__ u64 ldu(const float* p){ return *reinterpret_cast<const u64*>(p); }
__device__ __forceinline__ ulonglong2 ldp2(const float* p){ return *reinterpret_cast<const ulonglong2*>(p); }
__device__ __forceinline__ u64 pk2(float x, float y){ u64 r; asm("mov.b64 %0,{%1,%2};":"=l"(r):"f"(x),"f"(y)); return r; }
__device__ __forceinline__ float2 upk2(u64 v){ float2 f; asm("mov.b64 {%0,%1},%2;":"=f"(f.x),"=f"(f.y):"l"(v)); return f; }
__device__ __forceinline__ u64 fma2(u64 a,u64 b,u64 c){ u64 d; asm("fma.rn.f32x2 %0,%1,%2,%3;":"=l"(d):"l"(a),"l"(b),"l"(c)); return d; }

// Fast prep: P and G fused per block (2 independent FMA chains), deep unroll.
__global__ void prep_kernel(const float* __restrict__ Wq, const float* __restrict__ Wk,
                            const float* __restrict__ Wv, const float* __restrict__ Th,
                            const float* __restrict__ W1)
{
    const int bx = blockIdx.x, tid = threadIdx.x;
    if (bx < 128) {       // P[k][d] = sum_j Wq[j][k]*Wk[j][d] ; G[k][d] = sum_e Wv[e][k]*Th[d][e]
        const int d = bx;
        float accP = 0.f, accG = 0.f;
#pragma unroll 8
        for (int i = 0; i < 128; i++) {
            accP = fmaf(Wq[i*128 + tid], Wk[i*128 + d], accP);
            accG = fmaf(Wv[i*128 + tid], Th[d*128 + i], accG);
        }
        g_P[tid*128 + d] = accP * 0.08838834764831845f;
        g_G[tid*128 + d] = accG;
    } else {              // gU[k][j]
        const int bb = bx - 128;
        const int k  = bb*4 + (tid>>5);
        const int j0 = (tid & 31) * 2;
#pragma unroll
        for (int jj = 0; jj < 2; jj++) {
            const int j = j0 + jj;
            const float* w1row = (j < 32) ? (W1 + j*260) : (W1 + (j-32)*260 + 128);
            const float* wc    = (j < 32) ? Wq : Wk;
            float acc = 0.f;
#pragma unroll 8
            for (int d = 0; d < 128; d++) acc = fmaf(w1row[d], wc[d*128+k], acc);
            g_U[k*64 + j] = acc;
        }
    }
}

// -------- shared memory layout (float offsets) --------
#define OZ    0         // Z [32][132] = 4224   (persistent: ph1..ph8 residual)
#define OZT   4224      // ZT [128][34] = 4352 (ph0-2b) | HQ[32][36]@+0, HKT[32][33]@+1152 (ph4-5) | AZT [128][34] (ph7-8)
#define OC1   8576      // C1 [32][128] = 4096
#define OLOG  12672     // LOG [32][36] = 1152 | alphaT [32][33] (after softmax)
#define OSB   13824     // b1[32]@0, W2[32]@32, mask[32]@64, consts@96, W1e[32][4]@128  (256)
#define SMEMF 14080     // 56320 bytes -> 4 CTAs/SM

__global__ __launch_bounds__(TPB, 4)
void fused_gnn_kernel(const float* __restrict__ x, const float* __restrict__ edge,
                      const float* __restrict__ Aprior, const unsigned char* __restrict__ pmask,
                      const float* __restrict__ Wfuse, const float* __restrict__ W1,
                      const float* __restrict__ b1g, const float* __restrict__ W2g,
                      const float* __restrict__ b2g, const float* __restrict__ gammag,
                      const float* __restrict__ betag, const float* __restrict__ physw,
                      const float* __restrict__ priorw, float* __restrict__ out)
{
    extern __shared__ float sm[];
    const int tid = threadIdx.x;
    const int bt = blockIdx.x;
    const int b = bt >> 6, t = bt & 63;
    const int warp = tid >> 5, lane = tid & 31;

    // ---------------- Phase 0: stage Z + Z^T + small tensors ----------------
#pragma unroll
    for (int it = 0; it < 4; it++) {
        int idx = tid + it * TPB;              // idx = n*32 + dgroup
        int n = idx >> 5, dg = idx & 31;
        float4 v = ld4(x + ((((size_t)b*32 + n)*64 + t)*128) + dg*4);
        st4(sm + OZ + n*132 + dg*4, v);
        sm[OZT + (dg*4+0)*34 + n] = v.x;
        sm[OZT + (dg*4+1)*34 + n] = v.y;
        sm[OZT + (dg*4+2)*34 + n] = v.z;
        sm[OZT + (dg*4+3)*34 + n] = v.w;
    }
    if (tid < 32) {
        sm[OSB + tid]      = b1g[tid];
        sm[OSB + 32 + tid] = W2g[tid];
        sm[OSB + 64 + tid] = pmask[b*32 + tid] ? 1.f : 0.f;
        if (tid == 0) { sm[OSB+96] = physw[0]; sm[OSB+97] = priorw[0]; sm[OSB+98] = b2g[0]; }
    }
    if (tid >= 64 && tid < 192) {              // W1e [j][e]
        int i = tid - 64;
        sm[OSB + 128 + i] = W1[(i>>2)*260 + 256 + (i&3)];
    }
    __syncthreads();

    // ---------------- Phase 1: C1 = Z @ P -> OC1 (row-pair over n, P streamed) ----------------
    {
        const int nw = warp * 4;               // warp owns rows nw..nw+3 (2 pairs)
        u64 acc[2][4];
#pragma unroll
        for (int p = 0; p < 2; p++)
#pragma unroll
            for (int u = 0; u < 4; u++) acc[p][u] = 0ull;
#pragma unroll 4
        for (int k = 0; k < 128; k++) {
            u64 a0 = ldu(sm + OZT + k*34 + nw);
            u64 a1 = ldu(sm + OZT + k*34 + nw + 2);
            float4 w = __ldg(reinterpret_cast<const float4*>(g_P + k*128) + lane);
            u64 w0 = pk2(w.x, w.x), w1 = pk2(w.y, w.y), w2 = pk2(w.z, w.z), w3 = pk2(w.w, w.w);
            acc[0][0] = fma2(a0, w0, acc[0][0]);  acc[0][1] = fma2(a0, w1, acc[0][1]);
            acc[0][2] = fma2(a0, w2, acc[0][2]);  acc[0][3] = fma2(a0, w3, acc[0][3]);
            acc[1][0] = fma2(a1, w0, acc[1][0]);  acc[1][1] = fma2(a1, w1, acc[1][1]);
            acc[1][2] = fma2(a1, w2, acc[1][2]);  acc[1][3] = fma2(a1, w3, acc[1][3]);
        }
#pragma unroll
        for (int p = 0; p < 2; p++) {
            float2 f0 = upk2(acc[p][0]), f1 = upk2(acc[p][1]), f2 = upk2(acc[p][2]), f3 = upk2(acc[p][3]);
            st4(sm + OC1 + (nw + 2*p + 0)*128 + lane*4, make_float4(f0.x, f1.x, f2.x, f3.x));
            st4(sm + OC1 + (nw + 2*p + 1)*128 + lane*4, make_float4(f0.y, f1.y, f2.y, f3.y));
        }
    }
    __syncthreads();

    // ---------------- Phase 2: content = C1 @ Z^T -> LOG ----------------
    {
        u64 acc2[4] = {0ull, 0ull, 0ull, 0ull};
        for (int k = 0; k < 128; k += 4) {
            u64 zt01 = pk2(sm[OZT + (k+0)*34 + lane], sm[OZT + (k+1)*34 + lane]);
            u64 zt23 = pk2(sm[OZT + (k+2)*34 + lane], sm[OZT + (k+3)*34 + lane]);
#pragma unroll
            for (int i = 0; i < 4; i++) {
                ulonglong2 c2 = ldp2(sm + OC1 + (warp*4+i)*128 + k);
                acc2[i] = fma2(c2.x, zt01, acc2[i]);
                acc2[i] = fma2(c2.y, zt23, acc2[i]);
            }
        }
#pragma unroll
        for (int i = 0; i < 4; i++) {
            float2 f = upk2(acc2[i]);
            sm[OLOG + (warp*4+i)*36 + lane] = f.x + f.y;
        }
    }
    __syncthreads();   // ZT reads done -> OZT reusable for HQ/HKT

    // ---------------- Phase 4: H = Z @ gU (hq | hk), gU streamed from L2 ----------------
    {
        const int grp = warp >> 2, wg = warp & 3;
        const int r0 = wg * 8;
        const int j0g = grp * 32 + lane;
        u64 acc4[4] = {0ull, 0ull, 0ull, 0ull};
#pragma unroll 4
        for (int k = 0; k < 128; k += 4) {
            float wr[4];
#pragma unroll
            for (int u = 0; u < 4; u++) wr[u] = __ldg(&g_U[(k+u)*64 + j0g]);
#pragma unroll
            for (int h = 0; h < 2; h++) {
                float4 z[4];
#pragma unroll
                for (int i = 0; i < 4; i++) z[i] = ld4(sm + OZ + (r0 + h*4 + i)*132 + k);
#pragma unroll
                for (int u = 0; u < 4; u++) {
                    u64 w2 = pk2(wr[u], wr[u]);
#pragma unroll
                    for (int p = 0; p < 2; p++) {
                        float a0 = (u==0)?z[2*p].x:(u==1)?z[2*p].y:(u==2)?z[2*p].z:z[2*p].w;
                        float a1 = (u==0)?z[2*p+1].x:(u==1)?z[2*p+1].y:(u==2)?z[2*p+1].z:z[2*p+1].w;
                        acc4[h*2+p] = fma2(pk2(a0, a1), w2, acc4[h*2+p]);
                    }
                }
            }
        }
        if (grp == 0) {          // hq -> HQ[32][36] @ OZT
#pragma unroll
            for (int p = 0; p < 4; p++) {
                float2 f = upk2(acc4[p]);
                sm[OZT + (r0 + 2*p + 0)*36 + j0g] = f.x;
                sm[OZT + (r0 + 2*p + 1)*36 + j0g] = f.y;
            }
        } else {                 // hk -> HKT[j][n] [32][33] @ OZT+1152
            int j = j0g - 32;
#pragma unroll
            for (int p = 0; p < 4; p++) {
                float2 f = upk2(acc4[p]);
                sm[OZT + 1152 + j*33 + (r0 + 2*p + 0)] = f.x;
                sm[OZT + 1152 + j*33 + (r0 + 2*p + 1)] = f.y;
            }
        }
    }

    // ---------------- Prefetch edge / prior ----------------
    const int pn = tid >> 3, pm0 = (tid & 7) << 2;
    float4 e4[4]; float lpr[4];
    {
        const float wf0 = __ldg(Wfuse+0), wf1 = __ldg(Wfuse+1), wf2 = __ldg(Wfuse+2),
                    wf3 = __ldg(Wfuse+3), wf4 = __ldg(Wfuse+4);
#pragma unroll
        for (int mm = 0; mm < 4; mm++) {
            size_t pair = (size_t)bt*1024 + pn*32 + pm0 + mm;
            e4[mm] = ld4(edge + pair*4);
            const float* ap = Aprior + pair*5;
            float p = ap[0]*wf0 + ap[1]*wf1 + ap[2]*wf2 + ap[3]*wf3 + ap[4]*wf4;
            if (!isfinite(p)) p = 0.f;
            p = fmaxf(p, 0.f);
            lpr[mm] = logf(p + 1e-6f);
        }
    }
    __syncthreads();

    // ---------------- Phase 5: phys MLP + prior + logits ----------------
    {
        float ph[4] = {0.f, 0.f, 0.f, 0.f};
#pragma unroll
        for (int j = 0; j < 32; j += 4) {
            float4 hqv = ld4(sm + OZT + pn*36 + j);
            float4 b1v = ld4(sm + OSB + j);
            float4 w2v = ld4(sm + OSB + 32 + j);
            float hq4[4] = {hqv.x, hqv.y, hqv.z, hqv.w};
            float b14[4] = {b1v.x, b1v.y, b1v.z, b1v.w};
            float w24[4] = {w2v.x, w2v.y, w2v.z, w2v.w};
#pragma unroll
            for (int jj = 0; jj < 4; jj++) {
                int jc = j + jj;
                float hqb = hq4[jj] + b14[jj];
                float w2s = w24[jj];
                float4 we = ld4(sm + OSB + 128 + jc*4);
#pragma unroll
                for (int mm = 0; mm < 4; mm++) {
                    float h = hqb + sm[OZT + 1152 + jc*33 + pm0 + mm]
                            + e4[mm].x*we.x + e4[mm].y*we.y
                            + e4[mm].z*we.z + e4[mm].w*we.w;
                    h = fmaxf(h, 0.f);
                    ph[mm] = fmaf(h, w2s, ph[mm]);
                }
            }
        }
        float pw = sm[OSB+96], prw = sm[OSB+97], b2v = sm[OSB+98];
        float mn = sm[OSB + 64 + pn];
#pragma unroll
        for (int mm = 0; mm < 4; mm++) {
            float lg = sm[OLOG + pn*36 + pm0 + mm]
                     + pw * (ph[mm] + b2v)
                     + prw * lpr[mm];
            if (mn != 0.f || sm[OSB + 64 + pm0 + mm] != 0.f) lg = -1e9f;
            sm[OLOG + pn*36 + pm0 + mm] = lg;
        }
    }
    __syncthreads();

    // ---------------- Phase 6: softmax -> alphaT (transposed, in-place region) ----------------
    {
        float av[4];
#pragma unroll
        for (int q = 0; q < 4; q++) {
            int n = warp*4 + q;
            float v = sm[OLOG + n*36 + lane];
            float mx = v;
#pragma unroll
            for (int off = 16; off > 0; off >>= 1)
                mx = fmaxf(mx, __shfl_xor_sync(0xffffffffu, mx, off));
            float e = expf(v - mx);
            float s = e;
#pragma unroll
            for (int off = 16; off > 0; off >>= 1)
                s += __shfl_xor_sync(0xffffffffu, s, off);
            av[q] = e / s;
        }
        __syncthreads();   // all LOG reads done before overwriting region
#pragma unroll
        for (int q = 0; q < 4; q++)
            sm[OLOG + lane*33 + warp*4 + q] = av[q];   // alphaT[m=lane][n]
    }
    __syncthreads();

    // ---------------- Phase 7: AZT = (alpha @ Z)^T -> OZT (row-pair over e) ----------------
    {
        const int e0 = warp * 16;              // warp owns e rows e0..e0+15 (8 pairs)
        u64 acc7[8];
#pragma unroll
        for (int p = 0; p < 8; p++) acc7[p] = 0ull;
#pragma unroll 4
        for (int m = 0; m < 32; m++) {
            float a = sm[OLOG + m*33 + lane];  // alphaT[m][n=lane]
            u64 ad = pk2(a, a);
#pragma unroll
            for (int p = 0; p < 8; p++) {
                u64 zp = ldu(sm + OZ + m*132 + e0 + 2*p);
                acc7[p] = fma2(zp, ad, acc7[p]);
            }
        }
        __syncthreads();   // HQ/HKT reads (ph5) done; OZT free for AZT
#pragma unroll
        for (int p = 0; p < 8; p++) {
            float2 f = upk2(acc7[p]);
            sm[OZT + (e0 + 2*p + 0)*34 + lane] = f.x;
            sm[OZT + (e0 + 2*p + 1)*34 + lane] = f.y;
        }
    }
    __syncthreads();

    // ---------------- Phase 8+9: y = Z + AZ @ G (regs) -> LayerNorm -> store ----------------
    {
        const int nw = warp * 4;
        u64 acc[2][4];
#pragma unroll
        for (int p = 0; p < 2; p++)
#pragma unroll
            for (int u = 0; u < 4; u++) acc[p][u] = 0ull;
#pragma unroll 4
        for (int e = 0; e < 128; e++) {
            u64 a0 = ldu(sm + OZT + e*34 + nw);
            u64 a1 = ldu(sm + OZT + e*34 + nw + 2);
            float4 w = __ldg(reinterpret_cast<const float4*>(g_G + e*128) + lane);
            u64 w0 = pk2(w.x, w.x), w1 = pk2(w.y, w.y), w2 = pk2(w.z, w.z), w3 = pk2(w.w, w.w);
            acc[0][0] = fma2(a0, w0, acc[0][0]);  acc[0][1] = fma2(a0, w1, acc[0][1]);
            acc[0][2] = fma2(a0, w2, acc[0][2]);  acc[0][3] = fma2(a0, w3, acc[0][3]);
            acc[1][0] = fma2(a1, w0, acc[1][0]);  acc[1][1] = fma2(a1, w1, acc[1][1]);
            acc[1][2] = fma2(a1, w2, acc[1][2]);  acc[1][3] = fma2(a1, w3, acc[1][3]);
        }
        float4 gv = __ldg(reinterpret_cast<const float4*>(gammag + lane*4));
        float4 bv = __ldg(reinterpret_cast<const float4*>(betag + lane*4));
#pragma unroll
        for (int r = 0; r < 4; r++) {
            int n = nw + r;
            const int p = r >> 1;
            float2 f0 = upk2(acc[p][0]), f1 = upk2(acc[p][1]), f2 = upk2(acc[p][2]), f3 = upk2(acc[p][3]);
            float4 y;
            if ((r & 1) == 0) y = make_float4(f0.x, f1.x, f2.x, f3.x);
            else              y = make_float4(f0.y, f1.y, f2.y, f3.y);
            float4 zr = ld4(sm + OZ + n*132 + lane*4);
            y.x += zr.x; y.y += zr.y; y.z += zr.z; y.w += zr.w;
            float s  = y.x + y.y + y.z + y.w;
            float s2 = y.x*y.x + y.y*y.y + y.z*y.z + y.w*y.w;
#pragma unroll
            for (int off = 16; off > 0; off >>= 1) {
                s  += __shfl_xor_sync(0xffffffffu, s, off);
                s2 += __shfl_xor_sync(0xffffffffu, s2, off);
            }
            float mu   = s * (1.f/128.f);
            float var  = s2 * (1.f/128.f) - mu*mu;
            float rstd = rsqrtf(var + 1e-5f);
            float4 o;
            o.x = (y.x - mu)*rstd*gv.x + bv.x;
            o.y = (y.y - mu)*rstd*gv.y + bv.y;
            o.z = (y.z - mu)*rstd*gv.z + bv.z;
            o.w = (y.w - mu)*rstd*gv.w + bv.w;
            if (sm[OSB + 64 + n] != 0.f) o = make_float4(0.f, 0.f, 0.f, 0.f);
            reinterpret_cast<float4*>(out)[(((size_t)b*32 + n)*64 + t)*32 + lane] = o;
        }
    }
}

extern "C" void kernel_launch(void* const* d_in, const int* in_sizes, int n_in,
                              void* d_out, int out_size) {
    (void)in_sizes; (void)n_in; (void)out_size;
    const float* x      = (const float*)d_in[0];
    const float* edge   = (const float*)d_in[1];
    const float* Aprior = (const float*)d_in[2];
    const unsigned char* pmask = (const unsigned char*)d_in[3];
    const float* Wq     = (const float*)d_in[4];
    const float* Wk     = (const float*)d_in[5];
    const float* Wv     = (const float*)d_in[6];
    const float* Th     = (const float*)d_in[7];
    const float* Wfuse  = (const float*)d_in[8];
    const float* W1     = (const float*)d_in[9];
    const float* b1     = (const float*)d_in[10];
    const float* W2     = (const float*)d_in[11];
    const float* b2     = (const float*)d_in[12];
    const float* gamma  = (const float*)d_in[13];
    const float* beta   = (const float*)d_in[14];
    const float* physw  = (const float*)d_in[15];
    const float* priorw = (const float*)d_in[16];
    float* out = (float*)d_out;

    prep_kernel<<<160, 128>>>(Wq, Wk, Wv, Th, W1);

    cudaFuncSetAttribute(fused_gnn_kernel,
                         cudaFuncAttributeMaxDynamicSharedMemorySize, SMEMF * 4);
    fused_gnn_kernel<<<512, TPB, SMEMF * 4>>>(x, edge, Aprior, pmask, Wfuse, W1, b1, W2, b2,
                                              gamma, beta, physw, priorw, out);
}

// round 7
// speedup vs baseline: 1.0940x; 1.0940x over previous
#include <cuda_runtime.h>
#include <math.h>

#define TPB 256

typedef unsigned long long u64;
typedef unsigned int u32;

// Prologue-computed operands
__device__ float g_U[128*64];           // [k][j] for H-GEMM
// Fragment-packed tf32 hi/lo for P=(Wq^T Wk)/sqrt(d) and G=Wv^T Theta^T
// layout: ((kstep*16 + ntile)*32 + lane)*2 + {b0,b1}
__device__ u32 g_Pf_hi[16*16*32*2];
__device__ u32 g_Pf_lo[16*16*32*2];
__device__ u32 g_Gf_hi[16*16*32*2];
__device__ u32 g_Gf_lo[16*16*32*2];

__device__ __forceinline__ float4 ld4(const float* p){ return *reinterpret_cast<const float4*>(p); }
__device__ __forceinline__ void st4(float* p, float4 v){ *reinterpret_cast<float4*>(p)=v; }
__device__ __forceinline__ u64 ldu(const float* p){ return *reinterpret_cast<const u64*>(p); }
__device__ __forceinline__ void stu(float* p, u64 v){ *reinterpret_cast<u64*>(p)=v; }
__device__ __forceinline__ ulonglong2 ldp2(const float* p){ return *reinterpret_cast<const ulonglong2*>(p); }
__device__ __forceinline__ u64 pk2(float x, float y){ u64 r; asm("mov.b64 %0,{%1,%2};":"=l"(r):"f"(x),"f"(y)); return r; }
__device__ __forceinline__ float2 upk2(u64 v){ float2 f; asm("mov.b64 {%0,%1},%2;":"=f"(f.x),"=f"(f.y):"l"(v)); return f; }
__device__ __forceinline__ u64 fma2(u64 a,u64 b,u64 c){ u64 d; asm("fma.rn.f32x2 %0,%1,%2,%3;":"=l"(d):"l"(a),"l"(b),"l"(c)); return d; }
__device__ __forceinline__ u32 tf32h(float x){ u32 r; asm("cvt.rna.tf32.f32 %0,%1;":"=r"(r):"f"(x)); return r; }
__device__ __forceinline__ void mma8(float* c, const u32* a, const u32 b0, const u32 b1){
    asm("mma.sync.aligned.m16n8k8.row.col.f32.tf32.tf32.f32 "
        "{%0,%1,%2,%3},{%4,%5,%6,%7},{%8,%9},{%0,%1,%2,%3};"
        : "+f"(c[0]),"+f"(c[1]),"+f"(c[2]),"+f"(c[3])
        : "r"(a[0]),"r"(a[1]),"r"(a[2]),"r"(a[3]), "r"(b0),"r"(b1));
}

// ---------------- prep ----------------
// blocks 0..127: d = bx; thread = k. P[k][d], G[k][d] -> tf32 hi/lo fragment arrays.
// blocks 128..191: j = bx-128; thread = k. gU[k][j] (all loads coalesced/broadcast).
__global__ void prep_kernel(const float* __restrict__ Wq, const float* __restrict__ Wk,
                            const float* __restrict__ Wv, const float* __restrict__ Th,
                            const float* __restrict__ W1)
{
    const int bx = blockIdx.x, tid = threadIdx.x;
    if (bx < 128) {
        const int d = bx, k = tid;
        float accP = 0.f, accG = 0.f;
#pragma unroll 8
        for (int i = 0; i < 128; i++) {
            accP = fmaf(Wq[i*128 + k], Wk[i*128 + d], accP);
            accG = fmaf(Wv[i*128 + k], Th[d*128 + i], accG);
        }
        accP *= 0.08838834764831845f;
        const int ks = k >> 3, rin = k & 7, half = rin >> 2, tig = rin & 3;
        const int nt = d >> 3, gid = d & 7, ln = gid*4 + tig;
        const int idx = ((ks*16 + nt)*32 + ln)*2 + half;
        u32 ph = tf32h(accP);
        g_Pf_hi[idx] = ph;
        g_Pf_lo[idx] = tf32h(accP - __uint_as_float(ph));
        u32 gh = tf32h(accG);
        g_Gf_hi[idx] = gh;
        g_Gf_lo[idx] = tf32h(accG - __uint_as_float(gh));
    } else {
        const int j = bx - 128, k = tid;
        const float* w1row = (j < 32) ? (W1 + j*260) : (W1 + (j-32)*260 + 128);
        const float* wc    = (j < 32) ? Wq : Wk;
        float acc = 0.f;
#pragma unroll 8
        for (int d = 0; d < 128; d++) acc = fmaf(w1row[d], wc[d*128 + k], acc);
        g_U[k*64 + j] = acc;
    }
}

// -------- shared memory layout (float offsets) --------
#define OZ    0         // Z [32][132] = 4224   (persistent)
#define OZT   4224      // ZT [128][34]=4352 (ph0-2) | HQ[32][36]@+0, HKT[32][33]@+1152 (ph4-5) | y [32][132] (ph8-9)
#define OC1   8576      // C1 [32][132] = 4224 (ph1-2) -> AZ (ph7-8)
#define OLOG  12800     // LOG [32][36] = 1152 (content -> logits -> alpha)
#define OSB   13952     // b1[32]@0, W2[32]@32, mask[32]@64, consts@96, W1e[32][4]@128
#define SMEMF 14224     // 56896 bytes -> 4 CTAs/SM

// 3xTF32 mma GEMM: D[32x128] = A(sm,stride132)[32x128] @ Bfrag + optional (Z residual -> dst)
__device__ __forceinline__ void gemm_mma(const float* __restrict__ sA,
                                         const u32* __restrict__ Bhi, const u32* __restrict__ Blo,
                                         float* dst, const float* resid, int tid)
{
    const int warp = tid >> 5, lane = tid & 31;
    const int gid = lane >> 2, tig = lane & 3;
    const int mw = warp & 1;               // m-tile (rows mw*16 .. +15)
    const int nt0 = (warp >> 1) * 4;       // 4 n-tiles

    float c[4][4];
#pragma unroll
    for (int n = 0; n < 4; n++) { c[n][0]=0.f; c[n][1]=0.f; c[n][2]=0.f; c[n][3]=0.f; }

#pragma unroll 2
    for (int ks = 0; ks < 16; ks++) {
        const float* zb = sA + (mw*16 + gid)*132 + ks*8 + tig;
        float af0 = zb[0], af1 = zb[8*132], af2 = zb[4], af3 = zb[8*132 + 4];
        u32 ah[4], al[4];
        ah[0]=tf32h(af0); al[0]=tf32h(af0-__uint_as_float(ah[0]));
        ah[1]=tf32h(af1); al[1]=tf32h(af1-__uint_as_float(ah[1]));
        ah[2]=tf32h(af2); al[2]=tf32h(af2-__uint_as_float(ah[2]));
        ah[3]=tf32h(af3); al[3]=tf32h(af3-__uint_as_float(ah[3]));
#pragma unroll
        for (int nt = 0; nt < 4; nt++) {
            const int bidx = ((ks*16 + nt0 + nt)*32 + lane)*2;
            uint2 bh = *reinterpret_cast<const uint2*>(Bhi + bidx);
            uint2 bl = *reinterpret_cast<const uint2*>(Blo + bidx);
            mma8(c[nt], ah, bh.x, bh.y);
            mma8(c[nt], ah, bl.x, bl.y);
            mma8(c[nt], al, bh.x, bh.y);
        }
    }
    const int row0 = mw*16 + gid, row1 = row0 + 8;
#pragma unroll
    for (int nt = 0; nt < 4; nt++) {
        const int col = (nt0 + nt)*8 + 2*tig;
        float y00 = c[nt][0], y01 = c[nt][1], y10 = c[nt][2], y11 = c[nt][3];
        if (resid) {
            float2 r0 = *reinterpret_cast<const float2*>(resid + row0*132 + col);
            float2 r1 = *reinterpret_cast<const float2*>(resid + row1*132 + col);
            y00 += r0.x; y01 += r0.y; y10 += r1.x; y11 += r1.y;
        }
        *reinterpret_cast<float2*>(dst + row0*132 + col) = make_float2(y00, y01);
        *reinterpret_cast<float2*>(dst + row1*132 + col) = make_float2(y10, y11);
    }
}

__global__ __launch_bounds__(TPB, 4)
void fused_gnn_kernel(const float* __restrict__ x, const float* __restrict__ edge,
                      const float* __restrict__ Aprior, const unsigned char* __restrict__ pmask,
                      const float* __restrict__ Wfuse, const float* __restrict__ W1,
                      const float* __restrict__ b1g, const float* __restrict__ W2g,
                      const float* __restrict__ b2g, const float* __restrict__ gammag,
                      const float* __restrict__ betag, const float* __restrict__ physw,
                      const float* __restrict__ priorw, float* __restrict__ out)
{
    extern __shared__ float sm[];
    const int tid = threadIdx.x;
    const int bt = blockIdx.x;
    const int b = bt >> 6, t = bt & 63;
    const int warp = tid >> 5, lane = tid & 31;

    // ---------------- Phase 0: stage Z + Z^T + small tensors ----------------
#pragma unroll
    for (int it = 0; it < 4; it++) {
        int idx = tid + it * TPB;              // idx = n*32 + dgroup
        int n = idx >> 5, dg = idx & 31;
        float4 v = ld4(x + ((((size_t)b*32 + n)*64 + t)*128) + dg*4);
        st4(sm + OZ + n*132 + dg*4, v);
        sm[OZT + (dg*4+0)*34 + n] = v.x;
        sm[OZT + (dg*4+1)*34 + n] = v.y;
        sm[OZT + (dg*4+2)*34 + n] = v.z;
        sm[OZT + (dg*4+3)*34 + n] = v.w;
    }
    if (tid < 32) {
        sm[OSB + tid]      = b1g[tid];
        sm[OSB + 32 + tid] = W2g[tid];
        sm[OSB + 64 + tid] = pmask[b*32 + tid] ? 1.f : 0.f;
        if (tid == 0) { sm[OSB+96] = physw[0]; sm[OSB+97] = priorw[0]; sm[OSB+98] = b2g[0]; }
    }
    if (tid >= 64 && tid < 192) {              // W1e [j][e]
        int i = tid - 64;
        sm[OSB + 128 + i] = W1[(i>>2)*260 + 256 + (i&3)];
    }
    __syncthreads();

    // ---------------- Phase 1: C1 = Z @ P  (3xTF32 mma) ----------------
    gemm_mma(sm + OZ, g_Pf_hi, g_Pf_lo, sm + OC1, nullptr, tid);
    __syncthreads();

    // ---------------- Phase 2: content = C1 @ Z^T -> LOG ----------------
    {
        u64 acc2[4] = {0ull, 0ull, 0ull, 0ull};
        for (int k = 0; k < 128; k += 4) {
            u64 zt01 = pk2(sm[OZT + (k+0)*34 + lane], sm[OZT + (k+1)*34 + lane]);
            u64 zt23 = pk2(sm[OZT + (k+2)*34 + lane], sm[OZT + (k+3)*34 + lane]);
#pragma unroll
            for (int i = 0; i < 4; i++) {
                ulonglong2 c2 = ldp2(sm + OC1 + (warp*4+i)*132 + k);
                acc2[i] = fma2(c2.x, zt01, acc2[i]);
                acc2[i] = fma2(c2.y, zt23, acc2[i]);
            }
        }
#pragma unroll
        for (int i = 0; i < 4; i++) {
            float2 f = upk2(acc2[i]);
            sm[OLOG + (warp*4+i)*36 + lane] = f.x + f.y;
        }
    }
    __syncthreads();   // ZT reads done -> OZT reusable for HQ/HKT

    // ---------------- Phase 4: H = Z @ gU (hq | hk), gU streamed from L2 ----------------
    {
        const int grp = warp >> 2, wg = warp & 3;
        const int r0 = wg * 8;
        const int j0g = grp * 32 + lane;
        u64 acc4[4] = {0ull, 0ull, 0ull, 0ull};
#pragma unroll 4
        for (int k = 0; k < 128; k += 4) {
            float wr[4];
#pragma unroll
            for (int u = 0; u < 4; u++) wr[u] = __ldg(&g_U[(k+u)*64 + j0g]);
#pragma unroll
            for (int h = 0; h < 2; h++) {
                float4 z[4];
#pragma unroll
                for (int i = 0; i < 4; i++) z[i] = ld4(sm + OZ + (r0 + h*4 + i)*132 + k);
#pragma unroll
                for (int u = 0; u < 4; u++) {
                    u64 w2 = pk2(wr[u], wr[u]);
#pragma unroll
                    for (int p = 0; p < 2; p++) {
                        float a0 = (u==0)?z[2*p].x:(u==1)?z[2*p].y:(u==2)?z[2*p].z:z[2*p].w;
                        float a1 = (u==0)?z[2*p+1].x:(u==1)?z[2*p+1].y:(u==2)?z[2*p+1].z:z[2*p+1].w;
                        acc4[h*2+p] = fma2(pk2(a0, a1), w2, acc4[h*2+p]);
                    }
                }
            }
        }
        if (grp == 0) {          // hq -> HQ[32][36] @ OZT
#pragma unroll
            for (int p = 0; p < 4; p++) {
                float2 f = upk2(acc4[p]);
                sm[OZT + (r0 + 2*p + 0)*36 + j0g] = f.x;
                sm[OZT + (r0 + 2*p + 1)*36 + j0g] = f.y;
            }
        } else {                 // hk -> HKT[j][n] [32][33] @ OZT+1152
            int j = j0g - 32;
#pragma unroll
            for (int p = 0; p < 4; p++) {
                float2 f = upk2(acc4[p]);
                sm[OZT + 1152 + j*33 + (r0 + 2*p + 0)] = f.x;
                sm[OZT + 1152 + j*33 + (r0 + 2*p + 1)] = f.y;
            }
        }
    }

    // ---------------- Prefetch edge / prior ----------------
    const int pn = tid >> 3, pm0 = (tid & 7) << 2;
    float4 e4[4]; float lpr[4];
    {
        const float wf0 = __ldg(Wfuse+0), wf1 = __ldg(Wfuse+1), wf2 = __ldg(Wfuse+2),
                    wf3 = __ldg(Wfuse+3), wf4 = __ldg(Wfuse+4);
#pragma unroll
        for (int mm = 0; mm < 4; mm++) {
            size_t pair = (size_t)bt*1024 + pn*32 + pm0 + mm;
            e4[mm] = ld4(edge + pair*4);
            const float* ap = Aprior + pair*5;
            float p = ap[0]*wf0 + ap[1]*wf1 + ap[2]*wf2 + ap[3]*wf3 + ap[4]*wf4;
            if (!isfinite(p)) p = 0.f;
            p = fmaxf(p, 0.f);
            lpr[mm] = logf(p + 1e-6f);
        }
    }
    __syncthreads();

    // ---------------- Phase 5: phys MLP + prior + logits ----------------
    {
        float ph[4] = {0.f, 0.f, 0.f, 0.f};
#pragma unroll
        for (int j = 0; j < 32; j += 4) {
            float4 hqv = ld4(sm + OZT + pn*36 + j);
            float4 b1v = ld4(sm + OSB + j);
            float4 w2v = ld4(sm + OSB + 32 + j);
            float hq4[4] = {hqv.x, hqv.y, hqv.z, hqv.w};
            float b14[4] = {b1v.x, b1v.y, b1v.z, b1v.w};
            float w24[4] = {w2v.x, w2v.y, w2v.z, w2v.w};
#pragma unroll
            for (int jj = 0; jj < 4; jj++) {
                int jc = j + jj;
                float hqb = hq4[jj] + b14[jj];
                float w2s = w24[jj];
                float4 we = ld4(sm + OSB + 128 + jc*4);
#pragma unroll
                for (int mm = 0; mm < 4; mm++) {
                    float h = hqb + sm[OZT + 1152 + jc*33 + pm0 + mm]
                            + e4[mm].x*we.x + e4[mm].y*we.y
                            + e4[mm].z*we.z + e4[mm].w*we.w;
                    h = fmaxf(h, 0.f);
                    ph[mm] = fmaf(h, w2s, ph[mm]);
                }
            }
        }
        float pw = sm[OSB+96], prw = sm[OSB+97], b2v = sm[OSB+98];
        float mn = sm[OSB + 64 + pn];
#pragma unroll
        for (int mm = 0; mm < 4; mm++) {
            float lg = sm[OLOG + pn*36 + pm0 + mm]
                     + pw * (ph[mm] + b2v)
                     + prw * lpr[mm];
            if (mn != 0.f || sm[OSB + 64 + pm0 + mm] != 0.f) lg = -1e9f;
            sm[OLOG + pn*36 + pm0 + mm] = lg;
        }
    }
    __syncthreads();

    // ---------------- Phase 6: softmax (warp per 4 rows, in-place) ----------------
#pragma unroll
    for (int q = 0; q < 4; q++) {
        int n = warp*4 + q;
        float v = sm[OLOG + n*36 + lane];
        float mx = v;
#pragma unroll
        for (int off = 16; off > 0; off >>= 1)
            mx = fmaxf(mx, __shfl_xor_sync(0xffffffffu, mx, off));
        float e = expf(v - mx);
        float s = e;
#pragma unroll
        for (int off = 16; off > 0; off >>= 1)
            s += __shfl_xor_sync(0xffffffffu, s, off);
        sm[OLOG + n*36 + lane] = e / s;
    }
    __syncthreads();

    // ---------------- Phase 7: AZ = alpha @ Z -> OC1 (C1 dead) ----------------
    {
        const int grp = warp >> 2, wg = warp & 3;
        const int r0 = wg * 8;
        const int cb = grp * 64 + lane * 2;
        u64 acc[8];
#pragma unroll
        for (int i = 0; i < 8; i++) acc[i] = 0ull;
#pragma unroll
        for (int h = 0; h < 2; h++) {
#pragma unroll 2
            for (int k = 0; k < 32; k += 4) {
                float4 a[4];
#pragma unroll
                for (int i = 0; i < 4; i++) a[i] = ld4(sm + OLOG + (r0 + h*4 + i)*36 + k);
#pragma unroll
                for (int u = 0; u < 4; u++) {
                    u64 zw = ldu(sm + OZ + (k+u)*132 + cb);
#pragma unroll
                    for (int i = 0; i < 4; i++) {
                        float av = (u==0) ? a[i].x : (u==1) ? a[i].y : (u==2) ? a[i].z : a[i].w;
                        acc[h*4+i] = fma2(pk2(av, av), zw, acc[h*4+i]);
                    }
                }
            }
        }
        __syncthreads();   // C1 reads (ph2) long done; safe to overwrite OC1
#pragma unroll
        for (int i = 0; i < 8; i++)
            stu(sm + OC1 + (r0+i)*132 + cb, acc[i]);
    }
    __syncthreads();

    // ---------------- Phase 8: y = Z + AZ @ G (3xTF32 mma) -> OZT ----------------
    gemm_mma(sm + OC1, g_Gf_hi, g_Gf_lo, sm + OZT, sm + OZ, tid);
    __syncthreads();

    // ---------------- Phase 9: LayerNorm + masked store ----------------
    {
        float4 gv = __ldg(reinterpret_cast<const float4*>(gammag + lane*4));
        float4 bv = __ldg(reinterpret_cast<const float4*>(betag + lane*4));
#pragma unroll
        for (int q = 0; q < 4; q++) {
            int n = warp*4 + q;
            float4 y = ld4(sm + OZT + n*132 + lane*4);
            float s  = y.x + y.y + y.z + y.w;
            float s2 = y.x*y.x + y.y*y.y + y.z*y.z + y.w*y.w;
#pragma unroll
            for (int off = 16; off > 0; off >>= 1) {
                s  += __shfl_xor_sync(0xffffffffu, s, off);
                s2 += __shfl_xor_sync(0xffffffffu, s2, off);
            }
            float mu   = s * (1.f/128.f);
            float var  = s2 * (1.f/128.f) - mu*mu;
            float rstd = rsqrtf(var + 1e-5f);
            float4 o;
            o.x = (y.x - mu)*rstd*gv.x + bv.x;
            o.y = (y.y - mu)*rstd*gv.y + bv.y;
            o.z = (y.z - mu)*rstd*gv.z + bv.z;
            o.w = (y.w - mu)*rstd*gv.w + bv.w;
            if (sm[OSB + 64 + n] != 0.f) o = make_float4(0.f, 0.f, 0.f, 0.f);
            reinterpret_cast<float4*>(out)[(((size_t)b*32 + n)*64 + t)*32 + lane] = o;
        }
    }
}

extern "C" void kernel_launch(void* const* d_in, const int* in_sizes, int n_in,
                              void* d_out, int out_size) {
    (void)in_sizes; (void)n_in; (void)out_size;
    const float* x      = (const float*)d_in[0];
    const float* edge   = (const float*)d_in[1];
    const float* Aprior = (const float*)d_in[2];
    const unsigned char* pmask = (const unsigned char*)d_in[3];
    const float* Wq     = (const float*)d_in[4];
    const float* Wk     = (const float*)d_in[5];
    const float* Wv     = (const float*)d_in[6];
    const float* Th     = (const float*)d_in[7];
    const float* Wfuse  = (const float*)d_in[8];
    const float* W1     = (const float*)d_in[9];
    const float* b1     = (const float*)d_in[10];
    const float* W2     = (const float*)d_in[11];
    const float* b2     = (const float*)d_in[12];
    const float* gamma  = (const float*)d_in[13];
    const float* beta   = (const float*)d_in[14];
    const float* physw  = (const float*)d_in[15];
    const float* priorw = (const float*)d_in[16];
    float* out = (float*)d_out;

    prep_kernel<<<192, 128>>>(Wq, Wk, Wv, Th, W1);

    cudaFuncSetAttribute(fused_gnn_kernel,
                         cudaFuncAttributeMaxDynamicSharedMemorySize, SMEMF * 4);
    fused_gnn_kernel<<<512, TPB, SMEMF * 4>>>(x, edge, Aprior, pmask, Wfuse, W1, b1, W2, b2,
                                              gamma, beta, physw, priorw, out);
}